// round 8
// baseline (speedup 1.0000x reference)
#include <cuda_runtime.h>
#include <cuda_fp16.h>
#include <cstdint>

#define CCH   512
#define LSEQ  8192
#define NB    8
#define NPOS  (NB * LSEQ)
#define ICCH  32
#define NSTAGES (CCH / ICCH)       // 16
#define NBUF  3
#define WSZ   (3 * 512 * 512)
#define TAPSZ (512 * 512)

// ============================================================================
// Scratch (__device__ globals — no allocations allowed)
// ============================================================================
__device__ __half g_Xt16[(size_t)NPOS * CCH];   // fp16 mirror of residual stream
__device__ __half g_H16 [(size_t)NPOS * CCH];   // branch intermediate (fp16)
__device__ float  g_Xres[(size_t)NPOS * CCH];   // fp32 residual truth [pos][c]
__device__ __half g_U[(size_t)6 * 4 * TAPSZ];   // Winograd weights [w][t][oc][ic]
__device__ float  g_partial[6 * 32];
__device__ float  g_scales[6];

// ============================================================================
// Helpers
// ============================================================================
__device__ __forceinline__ uint32_t smem_u32(const void* p) {
    uint32_t a;
    asm("{ .reg .u64 t; cvta.to.shared.u64 t, %1; cvt.u32.u64 %0, t; }" : "=r"(a) : "l"(p));
    return a;
}
__device__ __forceinline__ void cp_async16(uint32_t dst, const void* src, uint32_t srcsize) {
    asm volatile("cp.async.cg.shared.global [%0], [%1], 16, %2;"
                 :: "r"(dst), "l"(src), "r"(srcsize) : "memory");
}
__device__ __forceinline__ void cp_commit() {
    asm volatile("cp.async.commit_group;" ::: "memory");
}
__device__ __forceinline__ void lds_v4(uint32_t* r, uint32_t addr) {
    asm volatile("ld.shared.v4.b32 {%0,%1,%2,%3}, [%4];"
                 : "=r"(r[0]), "=r"(r[1]), "=r"(r[2]), "=r"(r[3]) : "r"(addr));
}
__device__ __forceinline__ void mma_f16(float& d0, float& d1, float& d2, float& d3,
                                        uint32_t a0, uint32_t a1, uint32_t a2, uint32_t a3,
                                        uint32_t b0, uint32_t b1) {
    asm volatile("mma.sync.aligned.m16n8k16.row.col.f32.f16.f16.f32 "
                 "{%0,%1,%2,%3}, {%4,%5,%6,%7}, {%8,%9}, {%0,%1,%2,%3};"
                 : "+f"(d0), "+f"(d1), "+f"(d2), "+f"(d3)
                 : "r"(a0), "r"(a1), "r"(a2), "r"(a3), "r"(b0), "r"(b1));
}
__device__ __forceinline__ uint32_t hadd2u(uint32_t a, uint32_t b) {
    __half2 r = __hadd2(*reinterpret_cast<__half2*>(&a), *reinterpret_cast<__half2*>(&b));
    return *reinterpret_cast<uint32_t*>(&r);
}
__device__ __forceinline__ uint32_t hsub2u(uint32_t a, uint32_t b) {
    __half2 r = __hsub2(*reinterpret_cast<__half2*>(&a), *reinterpret_cast<__half2*>(&b));
    return *reinterpret_cast<uint32_t*>(&r);
}

// ============================================================================
// Weight prep: scale = mean(|w|)+1e-5; ternary; Winograd G-transform.
// U0=q0, U1=(q0+q1+q2)/2, U2=(q0-q1+q2)/2, U3=q2 — all exact in fp16.
// ============================================================================
#define RCHUNK 24576

__global__ void reduce_abs_kernel(const float* w0, const float* w1, const float* w2,
                                  const float* w3, const float* w4, const float* w5) {
    const float* ws[6] = {w0, w1, w2, w3, w4, w5};
    const float* w = ws[blockIdx.y];
    __shared__ float red[256];
    int n0 = blockIdx.x * RCHUNK;
    float s = 0.f;
    for (int i = threadIdx.x; i < RCHUNK; i += 256) s += fabsf(w[n0 + i]);
    red[threadIdx.x] = s;
    __syncthreads();
    for (int k = 128; k > 0; k >>= 1) {
        if (threadIdx.x < k) red[threadIdx.x] += red[threadIdx.x + k];
        __syncthreads();
    }
    if (threadIdx.x == 0) g_partial[blockIdx.y * 32 + blockIdx.x] = red[0];
}

__global__ void finalize_scale_kernel() {
    int t = threadIdx.x;
    if (t < 6) {
        float s = 0.f;
        for (int i = 0; i < 32; i++) s += g_partial[t * 32 + i];
        g_scales[t] = s / (float)WSZ + 1e-5f;
    }
}

__global__ void u_kernel(const float* w0, const float* w1, const float* w2,
                         const float* w3, const float* w4, const float* w5) {
    const float* ws[6] = {w0, w1, w2, w3, w4, w5};
    int widx = blockIdx.y;
    int idx = blockIdx.x * 256 + threadIdx.x;   // [0, TAPSZ)
    int o = idx >> 9;
    int i = idx & 511;
    float inv = 1.0f / g_scales[widx];
    float q[3];
#pragma unroll
    for (int t = 0; t < 3; t++) {
        float v = ws[widx][o * 1536 + i * 3 + t];
        q[t] = fmaxf(-1.f, fminf(1.f, rintf(v * inv)));
    }
    size_t base = (size_t)widx * 4 * TAPSZ + (size_t)o * 512 + i;
    g_U[base + 0 * TAPSZ] = __float2half_rn(q[0]);
    g_U[base + 1 * TAPSZ] = __float2half_rn(0.5f * (q[0] + q[1] + q[2]));
    g_U[base + 2 * TAPSZ] = __float2half_rn(0.5f * (q[0] - q[1] + q[2]));
    g_U[base + 3 * TAPSZ] = __float2half_rn(q[2]);
}

// ============================================================================
// Transposes
// ============================================================================
__global__ void transpose_in_kernel(const float* __restrict__ x,
                                    __half* __restrict__ xt16, float* __restrict__ xres) {
    __shared__ float tile[32][33];
    int l0 = blockIdx.x * 32, c0 = blockIdx.y * 32, bb = blockIdx.z;
    int tx = threadIdx.x, ty = threadIdx.y;
#pragma unroll
    for (int i = ty; i < 32; i += 8)
        tile[i][tx] = x[((size_t)(bb * CCH + c0 + i)) * LSEQ + l0 + tx];
    __syncthreads();
#pragma unroll
    for (int i = ty; i < 32; i += 8) {
        float v = tile[tx][i];
        size_t idx = ((size_t)(bb * LSEQ + l0 + i)) * CCH + c0 + tx;
        xt16[idx] = __float2half_rn(v);
        xres[idx] = v;
    }
}

__global__ void transpose_out_kernel(const float* __restrict__ xres, float* __restrict__ out) {
    __shared__ float tile[32][33];
    int l0 = blockIdx.x * 32, c0 = blockIdx.y * 32, bb = blockIdx.z;
    int tx = threadIdx.x, ty = threadIdx.y;
#pragma unroll
    for (int i = ty; i < 32; i += 8)
        tile[i][tx] = xres[((size_t)(bb * LSEQ + l0 + i)) * CCH + c0 + tx];
    __syncthreads();
#pragma unroll
    for (int i = ty; i < 32; i += 8)
        out[((size_t)(bb * CCH + c0 + i)) * LSEQ + l0 + tx] = tile[tx][i];
}

// ============================================================================
// Winograd F(2,3) conv. Per phase r (r = l mod DIL) an ordinary K=3 conv.
// Warp = 16 tiles x 32 oc x 4 Winograd points. Fragment row fr -> tile
// 2*(fr%8)+(fr/8): each thread owns two ADJACENT tiles -> 6 shared x rows.
// mode 0: out16 = lrelu(Y); mode 1: res += Y (fp32), res16 = fp16(res).
// ============================================================================
template<int DIL, int P, int MG, int OG>
__global__ void __launch_bounds__(MG * OG * 32, 1)
winconv_kernel(const __half* __restrict__ in, __half* __restrict__ out16,
               float* __restrict__ res, __half* __restrict__ res16,
               const float* __restrict__ bias, int widx, int mode) {
    constexpr int NOC    = OG * 32;
    constexpr int XROWS  = P + 2 * DIL;
    constexpr int UBYTES = 4 * NOC * 64;
    constexpr int XOFF   = UBYTES;
    constexpr int STAGE  = UBYTES + XROWS * 64;
    constexpr int NTHR   = MG * OG * 32;
    constexpr int UCHUNK = 4 * NOC * 4;
    constexpr int TCHUNK = UCHUNK + XROWS * 4;
    constexpr int BPS    = (LSEQ + P - 1) / P;
    constexpr int OGS    = (OG == 4) ? 2 : 1;

    extern __shared__ char smem[];
    const uint32_t sb = smem_u32(smem);

    const int tid  = threadIdx.x;
    const int lane = tid & 31;
    const int wid  = tid >> 5;
    const int warp_o = wid & (OG - 1);
    const int warp_g = wid >> OGS;

    const int oc0 = blockIdx.x * NOC;
    const int bi  = blockIdx.y % BPS;
    const int bb  = blockIdx.y / BPS;
    const int l0  = bi * P;

    const __half* ubase = g_U + (size_t)widx * 4 * TAPSZ;
    const __half* xbase = in + (size_t)bb * LSEQ * CCH;

    auto load_stage = [&](int s, int buf) {
        const int ic0 = s * ICCH;
        const uint32_t sbuf = sb + buf * STAGE;
        for (int t = tid; t < TCHUNK; t += NTHR) {
            if (t < UCHUNK) {
                int tp = t / (NOC * 4), rem = t - tp * (NOC * 4);
                int row = rem >> 2, q = rem & 3;
                const __half* src = ubase + (size_t)tp * TAPSZ + (size_t)(oc0 + row) * 512 + ic0 + q * 8;
                cp_async16(sbuf + tp * (NOC * 64) + row * 64 + q * 16, src, 16);
            } else {
                int t2 = t - UCHUNK;
                int rr = t2 >> 2, q = t2 & 3;
                int l = l0 + rr - DIL;
                uint32_t ok = (l >= 0 && l < LSEQ) ? 16u : 0u;
                int lcl = min(max(l, 0), LSEQ - 1);
                const __half* src = xbase + (size_t)lcl * CCH + ic0 + q * 8;
                cp_async16(sbuf + XOFF + rr * 64 + q * 16, src, ok);
            }
        }
        cp_commit();
    };

    float acc[4][4][4];
#pragma unroll
    for (int t = 0; t < 4; t++)
#pragma unroll
        for (int ni = 0; ni < 4; ni++)
#pragma unroll
            for (int r = 0; r < 4; r++) acc[t][ni][r] = 0.f;

    load_stage(0, 0);
    load_stage(1, 1);

    const int rsub = lane >> 2;
    const uint32_t coff = 16u * (lane & 3);
    const int G = (DIL == 1) ? 32 * warp_g : warp_g;   // pos-group / phase offset

#pragma unroll 1
    for (int s = 0; s < NSTAGES; ++s) {
        const int buf = s % NBUF;
        if (s + 2 < NSTAGES) {
            load_stage(s + 2, (s + 2) % NBUF);
            asm volatile("cp.async.wait_group 2;" ::: "memory");
        } else if (s + 1 < NSTAGES) {
            asm volatile("cp.async.wait_group 1;" ::: "memory");
        } else {
            asm volatile("cp.async.wait_group 0;" ::: "memory");
        }
        __syncthreads();

        const uint32_t sbuf = sb + buf * STAGE;

        // 6 shared x rows: rr = G + DIL*(4*rsub + si)
        uint32_t xr[6][4];
        const uint32_t xb = sbuf + XOFF + (uint32_t)(G + DIL * 4 * rsub) * 64 + coff;
#pragma unroll
        for (int si = 0; si < 6; si++) lds_v4(xr[si], xb + si * (DIL * 64));

#pragma unroll
        for (int t = 0; t < 4; ++t) {
            uint32_t wf[4][4];
            const uint32_t Wb = sbuf + t * (NOC * 64) + (warp_o * 32 + rsub) * 64 + coff;
#pragma unroll
            for (int ni = 0; ni < 4; ni++) lds_v4(wf[ni], Wb + ni * 8 * 64);

            // V in registers for the two tiles (B^T transform)
            uint32_t v0[4], v1[4];
#pragma unroll
            for (int j = 0; j < 4; j++) {
                if (t == 0)      { v0[j] = hsub2u(xr[0][j], xr[2][j]); v1[j] = hsub2u(xr[2][j], xr[4][j]); }
                else if (t == 1) { v0[j] = hadd2u(xr[1][j], xr[2][j]); v1[j] = hadd2u(xr[3][j], xr[4][j]); }
                else if (t == 2) { v0[j] = hsub2u(xr[2][j], xr[1][j]); v1[j] = hsub2u(xr[4][j], xr[3][j]); }
                else             { v0[j] = hsub2u(xr[1][j], xr[3][j]); v1[j] = hsub2u(xr[3][j], xr[5][j]); }
            }
#pragma unroll
            for (int ni = 0; ni < 4; ni++) {
                mma_f16(acc[t][ni][0], acc[t][ni][1], acc[t][ni][2], acc[t][ni][3],
                        v0[0], v1[0], v0[1], v1[1], wf[ni][0], wf[ni][1]);
                mma_f16(acc[t][ni][0], acc[t][ni][1], acc[t][ni][2], acc[t][ni][3],
                        v0[2], v1[2], v0[3], v1[3], wf[ni][2], wf[ni][3]);
            }
        }
        __syncthreads();
    }

    // Inverse transform: y0 = M0+M1+M2, y1 = M1-M2-M3 (fp32) + scale + bias.
    const float sc = g_scales[widx];
    const int obase = oc0 + warp_o * 32 + 2 * (lane & 3);
#pragma unroll
    for (int ni = 0; ni < 4; ni++) {
        const int oc = obase + ni * 8;
        const float2 bv = *reinterpret_cast<const float2*>(bias + oc);
        float vx[4], vy[4];
        vx[0] = acc[0][ni][0] + acc[1][ni][0] + acc[2][ni][0];
        vy[0] = acc[0][ni][1] + acc[1][ni][1] + acc[2][ni][1];
        vx[1] = acc[1][ni][0] - acc[2][ni][0] - acc[3][ni][0];
        vy[1] = acc[1][ni][1] - acc[2][ni][1] - acc[3][ni][1];
        vx[2] = acc[0][ni][2] + acc[1][ni][2] + acc[2][ni][2];
        vy[2] = acc[0][ni][3] + acc[1][ni][3] + acc[2][ni][3];
        vx[3] = acc[1][ni][2] - acc[2][ni][2] - acc[3][ni][2];
        vy[3] = acc[1][ni][3] - acc[2][ni][3] - acc[3][ni][3];
#pragma unroll
        for (int c = 0; c < 4; c++) {
            const int le = l0 + G + DIL * (4 * rsub + c);
            if (le < LSEQ) {
                float y0 = fmaf(sc, vx[c], bv.x);
                float y1 = fmaf(sc, vy[c], bv.y);
                size_t idx = (size_t)(bb * LSEQ + le) * CCH + oc;
                if (mode == 0) {
                    y0 = (y0 >= 0.f) ? y0 : 0.1f * y0;
                    y1 = (y1 >= 0.f) ? y1 : 0.1f * y1;
                    *reinterpret_cast<__half2*>(out16 + idx) = __floats2half2_rn(y0, y1);
                } else {
                    float2* rp = reinterpret_cast<float2*>(res + idx);
                    float2 r0 = *rp;
                    r0.x += y0; r0.y += y1;
                    *rp = r0;
                    *reinterpret_cast<__half2*>(res16 + idx) = __floats2half2_rn(r0.x, r0.y);
                }
            }
        }
    }
}

// ============================================================================
// Launch
// ============================================================================
extern "C" void kernel_launch(void* const* d_in, const int* in_sizes, int n_in,
                              void* d_out, int out_size) {
    (void)in_sizes; (void)n_in; (void)out_size;
    const float* x = (const float*)d_in[0];
    const float* w[6];
    const float* b[6];
    for (int br = 0; br < 3; br++)
        for (int j = 0; j < 2; j++) {
            w[br * 2 + j] = (const float*)d_in[1 + 4 * br + 2 * j];
            b[br * 2 + j] = (const float*)d_in[2 + 4 * br + 2 * j];
        }

    __half *Xt16, *H16;
    float *Xres;
    cudaGetSymbolAddress((void**)&Xt16, g_Xt16);
    cudaGetSymbolAddress((void**)&H16, g_H16);
    cudaGetSymbolAddress((void**)&Xres, g_Xres);

    const int SM_D1 = 3 * (4 * 128 * 64 + 98 * 64);    // 117120
    const int SM_D3 = 3 * (4 * 128 * 64 + 102 * 64);   // 117888
    const int SM_D5 = 3 * (4 * 64 * 64 + 170 * 64);    // 81792
    cudaFuncSetAttribute(winconv_kernel<1, 96, 3, 4>,
                         cudaFuncAttributeMaxDynamicSharedMemorySize, SM_D1);
    cudaFuncSetAttribute(winconv_kernel<3, 96, 3, 4>,
                         cudaFuncAttributeMaxDynamicSharedMemorySize, SM_D3);
    cudaFuncSetAttribute(winconv_kernel<5, 160, 5, 2>,
                         cudaFuncAttributeMaxDynamicSharedMemorySize, SM_D5);

    reduce_abs_kernel<<<dim3(32, 6), 256>>>(w[0], w[1], w[2], w[3], w[4], w[5]);
    finalize_scale_kernel<<<1, 32>>>();
    u_kernel<<<dim3(TAPSZ / 256, 6), 256>>>(w[0], w[1], w[2], w[3], w[4], w[5]);

    transpose_in_kernel<<<dim3(LSEQ / 32, CCH / 32, NB), dim3(32, 8)>>>(x, Xt16, Xres);

    const int BPS96 = (LSEQ + 95) / 96;     // 86
    const int BPS160 = (LSEQ + 159) / 160;  // 52

    // branch 0: dil=1
    winconv_kernel<1, 96, 3, 4><<<dim3(4, NB * BPS96), 384, SM_D1>>>(
        Xt16, H16, nullptr, nullptr, b[0], 0, 0);
    winconv_kernel<1, 96, 3, 4><<<dim3(4, NB * BPS96), 384, SM_D1>>>(
        H16, nullptr, Xres, Xt16, b[1], 1, 1);
    // branch 1: dil=3
    winconv_kernel<3, 96, 3, 4><<<dim3(4, NB * BPS96), 384, SM_D3>>>(
        Xt16, H16, nullptr, nullptr, b[2], 2, 0);
    winconv_kernel<1, 96, 3, 4><<<dim3(4, NB * BPS96), 384, SM_D1>>>(
        H16, nullptr, Xres, Xt16, b[3], 3, 1);
    // branch 2: dil=5
    winconv_kernel<5, 160, 5, 2><<<dim3(8, NB * BPS160), 320, SM_D5>>>(
        Xt16, H16, nullptr, nullptr, b[4], 4, 0);
    winconv_kernel<1, 96, 3, 4><<<dim3(4, NB * BPS96), 384, SM_D1>>>(
        H16, nullptr, Xres, Xt16, b[5], 5, 1);

    transpose_out_kernel<<<dim3(LSEQ / 32, CCH / 32, NB), dim3(32, 8)>>>(Xres, (float*)d_out);
}